// round 16
// baseline (speedup 1.0000x reference)
#include <cuda_runtime.h>
#include <cuda_fp16.h>
#include <cstdint>

// ---------------------------------------------------------------------------
#define TT   64
#define BB   32
#define NTB  2048
#define HID  256
#define FEAT 1152

__device__ __half g_a1[2048u*32*42*42];   // NHWC f16
__device__ __half g_a2[2048u*32*21*21];   // NHWC f16
__device__ __half g_xf[2048u*1152];       // f16, reference feature order
__device__ __half g_wih[768u*1152];       // W_ih pre-converted to f16
__device__ __half g_wc2[2*32*152];        // conv2 weights, chunk-major f16
__device__ __half g_wc34[4*32*152];       // conv3/conv4 weights, chunk-major f16
__device__ float  g_gi[2048u*768];
__device__ float  g_outs[2048u*256];
__device__ float  g_h[2][BB*HID];
__device__ unsigned g_bar_cnt = 0;
__device__ unsigned g_bar_phase = 0;

// ---------------------------------------------------------------------------
__device__ __forceinline__ void mma16(float4& d, uint32_t a0, uint32_t a1,
                                      uint32_t a2, uint32_t a3,
                                      uint32_t b0, uint32_t b1) {
    asm volatile("mma.sync.aligned.m16n8k16.row.col.f32.f16.f16.f32 "
        "{%0,%1,%2,%3},{%4,%5,%6,%7},{%8,%9},{%0,%1,%2,%3};"
        : "+f"(d.x), "+f"(d.y), "+f"(d.z), "+f"(d.w)
        : "r"(a0), "r"(a1), "r"(a2), "r"(a3), "r"(b0), "r"(b1));
}
__device__ __forceinline__ float eluf(float x) { return x > 0.f ? x : expm1f(x); }

__device__ __forceinline__ void cp16(void* smem, const void* g) {
    uint32_t s = (uint32_t)__cvta_generic_to_shared(smem);
    asm volatile("cp.async.ca.shared.global [%0], [%1], 16;" :: "r"(s), "l"(g));
}

// ---------------------------------------------------------------------------
// One-time weight conversions
// ---------------------------------------------------------------------------
__global__ void __launch_bounds__(256) wcvt(const float* __restrict__ W, __half* __restrict__ O) {
    int i = blockIdx.x * 256 + threadIdx.x;
    #pragma unroll
    for (int r = 0; r < 2; r++) {
        int idx = i + r * 110592;
        float4 v = *(const float4*)(W + idx*4);
        __half2 p0 = __floats2half2_rn(v.x, v.y);
        __half2 p1 = __floats2half2_rn(v.z, v.w);
        uint2 o; o.x = *(uint32_t*)&p0; o.y = *(uint32_t*)&p1;
        *(uint2*)(O + idx*4) = o;
    }
}

// conv weights OIHW f32 -> chunk-major f16: [ch][oc][tap*16 + c], stride 152
__global__ void __launch_bounds__(256) wcvtw(const float* __restrict__ w2,
        const float* __restrict__ w3, const float* __restrict__ w4) {
    for (int i = threadIdx.x + blockIdx.x*256; i < 2*32*152; i += gridDim.x*256) {
        int ch = i / (32*152);
        int r2 = i - ch*(32*152);
        int oc = r2 / 152, r = r2 - oc*152;
        float f = 0.f;
        if (r < 144) {
            int tap = r>>4, c = r&15;
            int ky = tap/3, kx = tap - ky*3;
            f = w2[((oc*32 + ch*16 + c)*3+ky)*3+kx];
        }
        g_wc2[i] = __float2half_rn(f);
    }
    for (int i = threadIdx.x + blockIdx.x*256; i < 4*32*152; i += gridDim.x*256) {
        int set = i / (32*152);
        int r2 = i - set*(32*152);
        int oc = r2 / 152, r = r2 - oc*152;
        const float* W = (set >> 1) ? w4 : w3;
        int ch = set & 1;
        float f = 0.f;
        if (r < 144) {
            int tap = r>>4, c = r&15;
            int ky = tap/3, kx = tap - ky*3;
            f = W[((oc*32 + ch*16 + c)*3+ky)*3+kx];
        }
        g_wc34[i] = __float2half_rn(f);
    }
}

// ---------------------------------------------------------------------------
// conv1 (unchanged)
// ---------------------------------------------------------------------------
template<int IH, int OH, int BAND>
__global__ void __launch_bounds__(256) conv1_f16(const float* __restrict__ in,
        const float* __restrict__ wgt, const float* __restrict__ bias,
        __half* __restrict__ out)
{
    constexpr int OW = OH, IW = IH;
    constexpr int RW = (IW+2)*4;
    constexpr int ROWS = 2*BAND + 1;
    constexpr int SIN = ROWS*RW;
    constexpr int APAD = 56;
    constexpr int NPIX = BAND*OW;
    constexpr int NT8 = (NPIX+7)/8;
    constexpr int NTW = (NT8+3)/4;
    constexpr int OHW = OH*OW;

    extern __shared__ __half sh[];
    __half* s_in = sh;
    __half* s_w  = sh + SIN;

    const int tid = threadIdx.x;
    const int n0 = blockIdx.x;
    const int oy0 = blockIdx.y * BAND;
    const int ybase = 2*oy0 - 1;

    for (int i = tid; i < SIN/8; i += 256) ((uint4*)s_in)[i] = make_uint4(0,0,0,0);

    for (int i = tid; i < 32*48; i += 256) {
        int oc = i/48, r = i - oc*48;
        int ky = r>>4, rr = r&15, kx = rr>>2, ic = rr&3;
        float v = (kx < 3) ? wgt[((oc*4+ic)*3+ky)*3+kx] : 0.f;
        s_w[oc*APAD + r] = __float2half_rn(v);
    }
    __syncthreads();

    const int y_lo = (ybase < 0) ? 0 : ybase;
    int y_hi = ybase + ROWS - 1; if (y_hi > IH-1) y_hi = IH-1;
    const int nrows = y_hi - y_lo + 1;

    for (int i = tid; i < nrows*IW; i += 256) {
        int x = i % IW; int yy = i / IW; int y = y_lo + yy;
        const float* p = in + (((size_t)n0*4)*IH + y)*IW + x;
        __half2 h01 = __floats2half2_rn(p[0], p[(size_t)IH*IW]);
        __half2 h23 = __floats2half2_rn(p[2*(size_t)IH*IW], p[3*(size_t)IH*IW]);
        __half* d = s_in + (y - ybase)*RW + (x+1)*4;
        *(__half2*)d = h01; *(__half2*)(d+2) = h23;
    }
    __syncthreads();

    const int lane = tid & 31, warp = tid >> 5;
    const int m0 = (warp & 1)*16;
    const int ng = warp >> 1;
    const int gq = lane >> 2, tq = lane & 3;

    int pixbase[NTW];
    #pragma unroll
    for (int j = 0; j < NTW; j++) {
        int tile = ng + 4*j;
        int p = tile*8 + gq;
        int pp = (p < NPIX) ? p : 0;
        int dy = pp / OW, ox = pp - dy*OW;
        pixbase[j] = 2*dy*RW + 8*ox + 2*tq;
    }

    float4 acc[NTW];
    #pragma unroll
    for (int j = 0; j < NTW; j++) acc[j] = make_float4(0.f,0.f,0.f,0.f);

    const __half* swr = s_w + (m0 + gq)*APAD + 2*tq;
    #pragma unroll
    for (int s = 0; s < 3; s++) {
        uint32_t a0 = *(const uint32_t*)(swr + s*16);
        uint32_t a1 = *(const uint32_t*)(swr + s*16 + 8*APAD);
        uint32_t a2 = *(const uint32_t*)(swr + s*16 + 8);
        uint32_t a3 = *(const uint32_t*)(swr + s*16 + 8*APAD + 8);
        int off = s*RW;
        #pragma unroll
        for (int j = 0; j < NTW; j++) {
            const __half* bp = s_in + pixbase[j] + off;
            mma16(acc[j], a0, a1, a2, a3,
                  *(const uint32_t*)bp, *(const uint32_t*)(bp + 8));
        }
    }

    const int oc = m0 + gq;
    const float b0v = __ldg(&bias[oc]);
    const float b8v = __ldg(&bias[oc+8]);
    __half* ob0 = out + ((size_t)n0*OHW + oy0*OW)*32;

    #pragma unroll
    for (int j = 0; j < NTW; j++) {
        int tile = ng + 4*j;
        if (tile >= NT8) continue;
        int pc = tile*8 + tq*2;
        if (pc < NPIX) {
            ob0[pc*32 + oc]   = __float2half_rn(eluf(acc[j].x + b0v));
            ob0[pc*32 + oc+8] = __float2half_rn(eluf(acc[j].z + b8v));
        }
        if (pc+1 < NPIX) {
            ob0[(pc+1)*32 + oc]   = __float2half_rn(eluf(acc[j].y + b0v));
            ob0[(pc+1)*32 + oc+8] = __float2half_rn(eluf(acc[j].w + b8v));
        }
    }
}

// ---------------------------------------------------------------------------
// conv2 v2: IC-chunked, slot stride 24 (16B-aligned), cp.async staging with
// shift-only per-iteration indexing. FIX: barrier between zero-fill and the
// async staging (cp.async data must not be overwritten by late zero-stores).
// ---------------------------------------------------------------------------
#define C2XS   24
#define C2RW   (44*C2XS)          // 1056
#define C2SIN  (15*C2RW)          // 15840
#define C2WSZ  (32*152)           // 4864
#define C2_SMEM ((C2SIN + C2WSZ) * 2)   // 41,408 B

__global__ void __launch_bounds__(256) conv2_f16(const __half* __restrict__ a1,
        const float* __restrict__ bias, __half* __restrict__ a2out)
{
    extern __shared__ __half sh[];
    __half* s_in = sh;
    __half* s_w  = sh + C2SIN;

    const int tid = threadIdx.x;
    const int n = blockIdx.x;
    const int oy0 = blockIdx.y * 7;
    const int ybase = 2*oy0 - 1;

    for (int i = tid; i < C2SIN/8; i += 256) ((uint4*)s_in)[i] = make_uint4(0,0,0,0);
    __syncthreads();   // zero must be visible before any cp.async staging lands

    const int y_lo = (ybase < 0) ? 0 : ybase;
    int y_hi = ybase + 14; if (y_hi > 41) y_hi = 41;
    const int nrows = y_hi - y_lo + 1;

    // staging decomposition: 84 uint4-units per row (x = u>>1, g = u&1),
    // 3 rows per wave -> 252 active threads; later indexing is pure strides.
    const int rphase = tid / 84;            // 0..3 (tid>=252 -> inactive)
    const int su = tid - rphase*84;
    const int sx = su >> 1, sg = su & 1;
    const bool sact = tid < 252;
    const __half* gsrc0 = a1 + (((size_t)n*42 + y_lo + rphase)*42 + sx)*32 + sg*8;
    __half* sdst0 = s_in + (y_lo - ybase + rphase)*C2RW + (sx+1)*C2XS + sg*8;

    const int lane = tid & 31, warp = tid >> 5;
    const int m0 = (warp & 1)*16;
    const int ng = warp >> 1;
    const int gq = lane >> 2, tq = lane & 3;
    const int oc = m0 + gq;

    int pixbase[5];
    #pragma unroll
    for (int j = 0; j < 5; j++) {
        int tile = ng + 4*j;
        int p = tile*8 + gq;
        int pp = (p < 147) ? p : 0;
        int dy = pp / 21, ox = pp - dy*21;
        pixbase[j] = 2*dy*C2RW + 2*ox*C2XS + 2*tq;
    }
    float4 acc[5];
    #pragma unroll
    for (int j = 0; j < 5; j++) acc[j] = make_float4(0.f,0.f,0.f,0.f);

    #pragma unroll
    for (int ch = 0; ch < 2; ch++) {
        if (ch) __syncthreads();
        for (int i = tid; i < C2WSZ/8; i += 256)
            cp16((uint4*)s_w + i, (const uint4*)(g_wc2 + ch*C2WSZ) + i);
        if (sact) {
            const __half* gs = gsrc0 + ch*16;
            __half* ds = sdst0;
            #pragma unroll
            for (int yy = 0; yy < 5; yy++) {
                int y = rphase + yy*3;
                if (y < nrows) cp16(ds, gs);
                gs += 3*42*32;
                ds += 3*C2RW;
            }
        }
        asm volatile("cp.async.commit_group;");
        asm volatile("cp.async.wait_group 0;");
        __syncthreads();

        const __half* swr = s_w + oc*152 + 2*tq;
        #pragma unroll
        for (int tap = 0; tap < 9; tap++) {
            uint32_t a0 = *(const uint32_t*)(swr + tap*16);
            uint32_t a1r = *(const uint32_t*)(swr + tap*16 + 8*152);
            uint32_t a2r = *(const uint32_t*)(swr + tap*16 + 8);
            uint32_t a3r = *(const uint32_t*)(swr + tap*16 + 8*152 + 8);
            int ky = tap/3, kx = tap - ky*3;
            int off = ky*C2RW + kx*C2XS;
            #pragma unroll
            for (int j = 0; j < 5; j++) {
                const __half* bp = s_in + pixbase[j] + off;
                mma16(acc[j], a0, a1r, a2r, a3r,
                      *(const uint32_t*)bp, *(const uint32_t*)(bp + 8));
            }
        }
    }

    const float b0v = __ldg(&bias[oc]);
    const float b8v = __ldg(&bias[oc+8]);
    __half* ob0 = a2out + ((size_t)n*441 + oy0*21)*32;
    #pragma unroll
    for (int j = 0; j < 5; j++) {
        int tile = ng + 4*j;
        if (tile >= 19) continue;
        int pc = tile*8 + tq*2;
        if (pc < 147) {
            ob0[pc*32 + oc]   = __float2half_rn(eluf(acc[j].x + b0v));
            ob0[pc*32 + oc+8] = __float2half_rn(eluf(acc[j].z + b8v));
        }
        if (pc+1 < 147) {
            ob0[(pc+1)*32 + oc]   = __float2half_rn(eluf(acc[j].y + b0v));
            ob0[(pc+1)*32 + oc+8] = __float2half_rn(eluf(acc[j].w + b8v));
        }
    }
}

// ---------------------------------------------------------------------------
// Fused conv3 + conv4, IC-chunked (R14 version — unchanged)
// ---------------------------------------------------------------------------
#define RW3C   460
#define SIN3C  5984
#define RW4C   260
#define PL4    3380
#define W34OFF (SIN3C + 2*PL4)
#define C34_SMEM ((W34OFF + 32*152) * 2)   // 35,216 B

template<int NTWP>
__device__ __forceinline__ void conv3_pass(const __half* __restrict__ a2,
        __half* __restrict__ s_in, __half* __restrict__ s_c4,
        __half* __restrict__ s_w, int n, int tid, int pass,
        int ng, int gq, int tq, int oc, float b0v, float b8v)
{
    const int npix  = pass ? 55 : 66;
    const int oyb   = pass ? 6 : 0;
    const int ybase = pass ? 11 : -1;
    const int ylo   = pass ? 11 : 0;
    const int yhi   = pass ? 20 : 11;
    const int nrows = yhi - ylo + 1;

    int pixbase[NTWP];
    #pragma unroll
    for (int j = 0; j < NTWP; j++) {
        int p = (ng + 4*j)*8 + gq;
        int pp = (p < npix) ? p : 0;
        int dy = pp / 11, ox = pp - dy*11;
        pixbase[j] = 2*dy*RW3C + 2*ox*20 + 2*tq;
    }
    float4 acc[NTWP];
    #pragma unroll
    for (int j = 0; j < NTWP; j++) acc[j] = make_float4(0.f,0.f,0.f,0.f);

    #pragma unroll
    for (int ch = 0; ch < 2; ch++) {
        __syncthreads();
        if (ch == 0) {
            for (int i = tid; i < SIN3C/8; i += 256) ((uint4*)s_in)[i] = make_uint4(0,0,0,0);
        }
        for (int i = tid; i < (32*152)/8; i += 256)
            ((uint4*)s_w)[i] = ((const uint4*)(g_wc34 + ch*32*152))[i];
        __syncthreads();
        for (int i = tid; i < nrows*21*4; i += 256) {
            int g = i & 3, q = i >> 2;
            int x = q % 21; int yy = q / 21;
            int y = ylo + yy;
            uint2 v = *(const uint2*)(a2 + (((size_t)n*21 + y)*21 + x)*32 + ch*16 + g*4);
            *(uint2*)(s_in + (y - ybase)*RW3C + (x+1)*20 + g*4) = v;
        }
        __syncthreads();

        const __half* swr = s_w + oc*152 + 2*tq;
        #pragma unroll
        for (int tap = 0; tap < 9; tap++) {
            uint32_t a0 = *(const uint32_t*)(swr + tap*16);
            uint32_t a1r = *(const uint32_t*)(swr + tap*16 + 8*152);
            uint32_t a2r = *(const uint32_t*)(swr + tap*16 + 8);
            uint32_t a3r = *(const uint32_t*)(swr + tap*16 + 8*152 + 8);
            int ky = tap/3, kx = tap - ky*3;
            int off = ky*RW3C + kx*20;
            #pragma unroll
            for (int j = 0; j < NTWP; j++) {
                const __half* bp = s_in + pixbase[j] + off;
                mma16(acc[j], a0, a1r, a2r, a3r,
                      *(const uint32_t*)bp, *(const uint32_t*)(bp + 8));
            }
        }
    }

    __half* plane = s_c4 + (oc >> 4)*PL4;
    const int cl = oc & 15;
    #pragma unroll
    for (int j = 0; j < NTWP; j++) {
        int pc = (ng + 4*j)*8 + tq*2;
        #pragma unroll
        for (int u = 0; u < 2; u++) {
            int p = pc + u;
            if (p < npix) {
                int y = p / 11, x = p - y*11;
                __half* d = plane + (oyb + y + 1)*RW4C + (x+1)*20;
                float v0 = (u == 0) ? acc[j].x : acc[j].y;
                float v8 = (u == 0) ? acc[j].z : acc[j].w;
                d[cl]   = __float2half_rn(eluf(v0 + b0v));
                d[cl+8] = __float2half_rn(eluf(v8 + b8v));
            }
        }
    }
}

__global__ void __launch_bounds__(256) conv34_f16(const __half* __restrict__ a2,
        const float* __restrict__ b3f, const float* __restrict__ b4f,
        __half* __restrict__ xf)
{
    extern __shared__ __half sh[];
    __half* s_in = sh;
    __half* s_c4 = sh + SIN3C;
    __half* s_w  = sh + W34OFF;

    const int tid = threadIdx.x;
    const int n = blockIdx.x;

    for (int i = tid; i < 2*PL4/8; i += 256) ((uint4*)s_c4)[i] = make_uint4(0,0,0,0);

    const int lane = tid & 31, warp = tid >> 5;
    const int m0 = (warp & 1)*16;
    const int ng = warp >> 1;
    const int gq = lane >> 2, tq = lane & 3;
    const int oc = m0 + gq;

    const float b30 = __ldg(&b3f[oc]);
    const float b38 = __ldg(&b3f[oc+8]);

    conv3_pass<3>(a2, s_in, s_c4, s_w, n, tid, 0, ng, gq, tq, oc, b30, b38);
    conv3_pass<2>(a2, s_in, s_c4, s_w, n, tid, 1, ng, gq, tq, oc, b30, b38);

    int pixbase[2];
    #pragma unroll
    for (int j = 0; j < 2; j++) {
        int tile = ng + 4*j;
        int p = tile*8 + gq;
        int pp = (p < 36) ? p : 0;
        int dy = pp / 6, ox = pp - dy*6;
        pixbase[j] = 2*dy*RW4C + 2*ox*20 + 2*tq;
    }
    float4 acc[2];
    acc[0] = make_float4(0.f,0.f,0.f,0.f); acc[1] = acc[0];

    #pragma unroll
    for (int ch = 0; ch < 2; ch++) {
        __syncthreads();
        for (int i = tid; i < (32*152)/8; i += 256)
            ((uint4*)s_w)[i] = ((const uint4*)(g_wc34 + (2+ch)*32*152))[i];
        __syncthreads();
        const __half* plane = s_c4 + ch*PL4;
        const __half* swr = s_w + oc*152 + 2*tq;
        #pragma unroll
        for (int tap = 0; tap < 9; tap++) {
            uint32_t a0 = *(const uint32_t*)(swr + tap*16);
            uint32_t a1r = *(const uint32_t*)(swr + tap*16 + 8*152);
            uint32_t a2r = *(const uint32_t*)(swr + tap*16 + 8);
            uint32_t a3r = *(const uint32_t*)(swr + tap*16 + 8*152 + 8);
            int ky = tap/3, kx = tap - ky*3;
            int off = ky*RW4C + kx*20;
            #pragma unroll
            for (int j = 0; j < 2; j++) {
                const __half* bp = plane + pixbase[j] + off;
                mma16(acc[j], a0, a1r, a2r, a3r,
                      *(const uint32_t*)bp, *(const uint32_t*)(bp + 8));
            }
        }
    }

    const float b0v = __ldg(&b4f[oc]);
    const float b8v = __ldg(&b4f[oc+8]);
    __half* ob = xf + (size_t)n*1152;
    #pragma unroll
    for (int j = 0; j < 2; j++) {
        int tile = ng + 4*j;
        if (tile >= 5) continue;
        int pc = tile*8 + tq*2;
        if (pc < 36) {
            ob[oc*36 + pc]     = __float2half_rn(eluf(acc[j].x + b0v));
            ob[(oc+8)*36 + pc] = __float2half_rn(eluf(acc[j].z + b8v));
        }
        if (pc+1 < 36) {
            ob[oc*36 + pc+1]     = __float2half_rn(eluf(acc[j].y + b0v));
            ob[(oc+8)*36 + pc+1] = __float2half_rn(eluf(acc[j].w + b8v));
        }
    }
}

// ---------------------------------------------------------------------------
// gi[2048,768] = xf(f16) @ Wih(f16)^T + b_ih — 2-stage cp.async pipeline.
// ---------------------------------------------------------------------------
__global__ void __launch_bounds__(256) gemm_f16(const __half* __restrict__ A,
        const __half* __restrict__ B, const float* __restrict__ bias,
        float* __restrict__ C)
{
    constexpr int ST = 48;
    __shared__ __half As[2][64*ST], Bs[2][64*ST];
    const int bm = blockIdx.y*64, bn = blockIdx.x*64;
    const int tid = threadIdx.x, lane = tid&31, warp = tid>>5;
    const int wm = (warp&1)*32, wn = (warp>>1)*16;
    const int gq = lane>>2, tq = lane&3;
    const int ldr = tid>>2, ldc = (tid&3)*8;

    const __half* Ag = A + (size_t)(bm+ldr)*FEAT + ldc;
    const __half* Bg = B + (size_t)(bn+ldr)*FEAT + ldc;

    float4 acc[2][2];
    #pragma unroll
    for (int i = 0; i < 2; i++)
        #pragma unroll
        for (int j = 0; j < 2; j++) acc[i][j] = make_float4(0.f,0.f,0.f,0.f);

    cp16(&As[0][ldr*ST + ldc], Ag);
    cp16(&Bs[0][ldr*ST + ldc], Bg);
    asm volatile("cp.async.commit_group;");

    #pragma unroll 1
    for (int i = 0; i < 36; i++) {
        if (i + 1 < 36) {
            int st = (i+1)&1;
            cp16(&As[st][ldr*ST + ldc], Ag + (i+1)*32);
            cp16(&Bs[st][ldr*ST + ldc], Bg + (i+1)*32);
            asm volatile("cp.async.commit_group;");
            asm volatile("cp.async.wait_group 1;");
        } else {
            asm volatile("cp.async.wait_group 0;");
        }
        __syncthreads();
        const int cs = i&1;
        #pragma unroll
        for (int s = 0; s < 2; s++) {
            #pragma unroll
            for (int mi = 0; mi < 2; mi++) {
                const __half* ap = &As[cs][(wm + mi*16 + gq)*ST + s*16 + 2*tq];
                uint32_t a0 = *(const uint32_t*)ap;
                uint32_t a1 = *(const uint32_t*)(ap + 8*ST);
                uint32_t a2 = *(const uint32_t*)(ap + 8);
                uint32_t a3 = *(const uint32_t*)(ap + 8*ST + 8);
                #pragma unroll
                for (int ni = 0; ni < 2; ni++) {
                    const __half* bp = &Bs[cs][(wn + ni*8 + gq)*ST + s*16 + 2*tq];
                    mma16(acc[mi][ni], a0, a1, a2, a3,
                          *(const uint32_t*)bp, *(const uint32_t*)(bp + 8));
                }
            }
        }
        __syncthreads();
    }
    #pragma unroll
    for (int mi = 0; mi < 2; mi++) {
        #pragma unroll
        for (int ni = 0; ni < 2; ni++) {
            int row = bm + wm + mi*16 + gq;
            int col = bn + wn + ni*8 + tq*2;
            float bb0 = __ldg(&bias[col]), bb1 = __ldg(&bias[col+1]);
            C[(size_t)row*768 + col]       = acc[mi][ni].x + bb0;
            C[(size_t)row*768 + col + 1]   = acc[mi][ni].y + bb1;
            C[(size_t)(row+8)*768 + col]   = acc[mi][ni].z + bb0;
            C[(size_t)(row+8)*768 + col+1] = acc[mi][ni].w + bb1;
        }
    }
}

// ---------------------------------------------------------------------------
// Persistent GRU (frozen)
// ---------------------------------------------------------------------------
#define GRU_BLOCKS 64
#define GRU_THREADS 256

__device__ __forceinline__ void grid_barrier(unsigned target) {
    __threadfence();
    __syncthreads();
    if (threadIdx.x == 0) {
        unsigned v = atomicAdd(&g_bar_cnt, 1);
        if (v == GRU_BLOCKS - 1) {
            g_bar_cnt = 0;
            __threadfence();
            atomicAdd(&g_bar_phase, 1);
        } else {
            while ((int)(*(volatile unsigned*)&g_bar_phase - target) < 0) { __nanosleep(16); }
        }
        __threadfence();
    }
    __syncthreads();
}

__global__ void gru_kernel(const float* __restrict__ rnn_in, const float* __restrict__ mask,
                           const float* __restrict__ W_hh, const float* __restrict__ b_hh,
                           const float* __restrict__ gi_all, float* __restrict__ outs,
                           float* __restrict__ hfin) {
    __shared__ float s_w[12*256];
    __shared__ float s_h[32*256];
    __shared__ float s_p[3*256];

    const int tid = threadIdx.x;
    const int bx  = blockIdx.x;

    for (int i = tid; i < 12*64; i += GRU_THREADS) {
        int rl = i >> 6, kq = i & 63;
        int gate = rl >> 2, gj2 = rl & 3;
        float4 w = *(const float4*)&W_hh[(size_t)(gate*256 + bx*4 + gj2)*256 + kq*4];
        *(float4*)&s_w[rl*256 + kq*4] = w;
    }
    if (bx == 0) {
        for (int i = tid; i < BB*HID; i += GRU_THREADS) g_h[0][i] = rnn_in[i];
    }
    unsigned tgt = *(volatile unsigned*)&g_bar_phase;
    grid_barrier(++tgt);

    const int half = tid >> 7;
    const int r    = tid & 127;
    const int gj = r >> 5, b = r & 31;
    const int g = bx*4 + gj;
    const int c = b & 7;
    const float br = __ldg(&b_hh[g]);
    const float bz = __ldg(&b_hh[256 + g]);
    const float bn = __ldg(&b_hh[512 + g]);

    float4* s_h4 = (float4*)s_h;
    const float4* s_w4 = (const float4*)s_w;

    for (int t = 0; t < TT; t++) {
        float gir = 0.f, giz = 0.f, gin = 0.f;
        if (tid < 128) {
            const float* gi = gi_all + (size_t)(t*32 + b)*768;
            gir = __ldg(&gi[g]); giz = __ldg(&gi[256 + g]); gin = __ldg(&gi[512 + g]);
        }
        const float* hprev = g_h[t & 1];
        for (int i = tid; i < 32*64; i += GRU_THREADS) {
            int bb = i >> 6, kq = i & 63;
            float m = __ldg(&mask[t*32 + bb]);
            float4 hv = __ldcg((const float4*)&hprev[bb*256 + kq*4]);
            hv.x *= m; hv.y *= m; hv.z *= m; hv.w *= m;
            s_h4[bb*64 + (kq ^ (bb & 7))] = hv;
        }
        __syncthreads();

        float4 ar = make_float4(0.f,0.f,0.f,0.f), az = ar, an = ar;
        const float4* hrow = s_h4 + b*64;
        const float4* wr4 = s_w4 + (0 + gj)*64;
        const float4* wz4 = s_w4 + (4 + gj)*64;
        const float4* wn4 = s_w4 + (8 + gj)*64;
        #pragma unroll 8
        for (int kq = 0; kq < 32; kq++) {
            int kqg = half*32 + kq;
            float4 h = hrow[kqg ^ c];
            float4 wr = wr4[kqg], wz = wz4[kqg], wn = wn4[kqg];
            ar.x += h.x*wr.x; ar.y += h.y*wr.y; ar.z += h.z*wr.z; ar.w += h.w*wr.w;
            az.x += h.x*wz.x; az.y += h.y*wz.y; az.z += h.z*wz.z; az.w += h.w*wz.w;
            an.x += h.x*wn.x; an.y += h.y*wn.y; an.z += h.z*wn.z; an.w += h.w*wn.w;
        }
        s_p[0*256 + tid] = ar.x + ar.y + ar.z + ar.w;
        s_p[1*256 + tid] = az.x + az.y + az.z + az.w;
        s_p[2*256 + tid] = an.x + an.y + an.z + an.w;
        __syncthreads();
        if (tid < 128) {
            float ghr = s_p[0*256 + tid] + s_p[0*256 + tid + 128] + br;
            float ghz = s_p[1*256 + tid] + s_p[1*256 + tid + 128] + bz;
            float ghn = s_p[2*256 + tid] + s_p[2*256 + tid + 128] + bn;
            float rr = 1.f / (1.f + expf(-(gir + ghr)));
            float zz = 1.f / (1.f + expf(-(giz + ghz)));
            float nn = tanhf(gin + rr*ghn);
            float hold = s_h[b*256 + (((g>>2) ^ c)<<2) + (g&3)];
            float hn = (1.f - zz)*nn + zz*hold;
            g_h[(t + 1) & 1][b*256 + g] = hn;
            outs[(size_t)(t*32 + b)*256 + g] = hn;
            if (t == TT - 1) hfin[b*256 + g] = hn;
        }
        grid_barrier(++tgt);
    }
}

// ---------------------------------------------------------------------------
// Heads
// ---------------------------------------------------------------------------
__global__ void heads_kernel(const float* __restrict__ outs, const int* __restrict__ actions,
                             const float* __restrict__ Wc, const float* __restrict__ bc,
                             const float* __restrict__ Wa, const float* __restrict__ ba,
                             float* __restrict__ d_out) {
    int warp = (blockIdx.x * blockDim.x + threadIdx.x) >> 5;
    int lane = threadIdx.x & 31;
    if (warp >= NTB) return;
    const float* o = outs + (size_t)warp * 256;

    float acc[13];
    #pragma unroll
    for (int g = 0; g < 13; g++) acc[g] = 0.f;
    #pragma unroll
    for (int i = 0; i < 8; i++) {
        int k = lane + 32*i;
        float x = o[k];
        acc[0] += x * __ldg(&Wc[k]);
        #pragma unroll
        for (int g = 0; g < 12; g++) acc[1 + g] += x * __ldg(&Wa[g*256 + k]);
    }
    #pragma unroll
    for (int g = 0; g < 13; g++) {
        #pragma unroll
        for (int s = 16; s > 0; s >>= 1) acc[g] += __shfl_xor_sync(0xFFFFFFFFu, acc[g], s);
    }
    if (lane == 0) {
        float v = acc[0] + bc[0];
        float l[12];
        float m = -1e30f;
        #pragma unroll
        for (int g = 0; g < 12; g++) { l[g] = acc[1 + g] + ba[g]; m = fmaxf(m, l[g]); }
        float s = 0.f, sl = 0.f;
        #pragma unroll
        for (int g = 0; g < 12; g++) {
            float e = expf(l[g] - m);
            s += e; sl += e * l[g];
        }
        float logZ = m + logf(s);
        int a = actions[warp];
        d_out[warp]        = v;
        d_out[2048 + warp] = (float)a;
        d_out[4096 + warp] = l[a] - logZ;
        d_out[6144 + warp] = logZ - sl / s;
    }
}

// ---------------------------------------------------------------------------
// Host launcher
// ---------------------------------------------------------------------------
#define C1_SMEM ((13*344 + 32*56) * 2)

extern "C" void kernel_launch(void* const* d_in, const int* in_sizes, int n_in,
                              void* d_out, int out_size) {
    const float* inputs = (const float*)d_in[0];
    const float* rnn_in = (const float*)d_in[1];
    const float* mask   = (const float*)d_in[2];
    const int*   actions= (const int*)  d_in[3];
    const float* w1 = (const float*)d_in[4];  const float* b1 = (const float*)d_in[5];
    const float* w2 = (const float*)d_in[6];  const float* b2 = (const float*)d_in[7];
    const float* w3 = (const float*)d_in[8];  const float* b3 = (const float*)d_in[9];
    const float* w4 = (const float*)d_in[10]; const float* b4 = (const float*)d_in[11];
    const float* W_ih = (const float*)d_in[12];
    const float* W_hh = (const float*)d_in[13];
    const float* b_ih = (const float*)d_in[14];
    const float* b_hh = (const float*)d_in[15];
    const float* Wc = (const float*)d_in[16]; const float* bc = (const float*)d_in[17];
    const float* Wa = (const float*)d_in[18]; const float* ba = (const float*)d_in[19];
    float* out = (float*)d_out;

    __half *a1, *a2, *xf, *wih;
    float *gi, *outs;
    cudaGetSymbolAddress((void**)&a1, g_a1);
    cudaGetSymbolAddress((void**)&a2, g_a2);
    cudaGetSymbolAddress((void**)&xf, g_xf);
    cudaGetSymbolAddress((void**)&wih, g_wih);
    cudaGetSymbolAddress((void**)&gi, g_gi);
    cudaGetSymbolAddress((void**)&outs, g_outs);

    cudaFuncSetAttribute((conv1_f16<84,42,6>), cudaFuncAttributeMaxDynamicSharedMemorySize, C1_SMEM);
    cudaFuncSetAttribute(conv2_f16,            cudaFuncAttributeMaxDynamicSharedMemorySize, C2_SMEM);
    cudaFuncSetAttribute(conv34_f16,           cudaFuncAttributeMaxDynamicSharedMemorySize, C34_SMEM);

    wcvt<<<432, 256>>>(W_ih, wih);
    wcvtw<<<16, 256>>>(w2, w3, w4);
    conv1_f16<84,42,6> <<<dim3(NTB,7), 256, C1_SMEM>>>(inputs, w1, b1, a1);
    conv2_f16          <<<dim3(NTB,3), 256, C2_SMEM>>>(a1, b2, a2);
    conv34_f16         <<<NTB, 256, C34_SMEM>>>(a2, b3, b4, xf);

    gemm_f16<<<dim3(768/64, 2048/64), 256>>>(xf, wih, b_ih, gi);

    gru_kernel<<<GRU_BLOCKS, GRU_THREADS>>>(rnn_in, mask, W_hh, b_hh, gi, outs, out + 8192);

    heads_kernel<<<256, 256>>>(outs, actions, Wc, bc, Wa, ba, out);
}

// round 17
// speedup vs baseline: 1.0360x; 1.0360x over previous
#include <cuda_runtime.h>
#include <cuda_fp16.h>
#include <cstdint>

// ---------------------------------------------------------------------------
#define TT   64
#define BB   32
#define NTB  2048
#define HID  256
#define FEAT 1152

__device__ __half g_a1[2048u*32*42*42];   // NHWC f16
__device__ __half g_a2[2048u*32*21*21];   // NHWC f16
__device__ __half g_xf[2048u*1152];       // f16, reference feature order
__device__ __half g_wih[768u*1152];       // W_ih pre-converted to f16
__device__ __half g_wc2[2*32*152];        // conv2 weights, chunk-major f16
__device__ __half g_wc34[4*32*152];       // conv3/conv4 weights, chunk-major f16
__device__ float  g_gi[2048u*768];
__device__ float  g_outs[2048u*256];
__device__ float  g_h[2][BB*HID];
__device__ unsigned g_bar_cnt = 0;
__device__ unsigned g_bar_phase = 0;

// ---------------------------------------------------------------------------
__device__ __forceinline__ void mma16(float4& d, uint32_t a0, uint32_t a1,
                                      uint32_t a2, uint32_t a3,
                                      uint32_t b0, uint32_t b1) {
    asm volatile("mma.sync.aligned.m16n8k16.row.col.f32.f16.f16.f32 "
        "{%0,%1,%2,%3},{%4,%5,%6,%7},{%8,%9},{%0,%1,%2,%3};"
        : "+f"(d.x), "+f"(d.y), "+f"(d.z), "+f"(d.w)
        : "r"(a0), "r"(a1), "r"(a2), "r"(a3), "r"(b0), "r"(b1));
}
__device__ __forceinline__ float eluf(float x) { return x > 0.f ? x : expm1f(x); }

__device__ __forceinline__ void cp16(void* smem, const void* g) {
    uint32_t s = (uint32_t)__cvta_generic_to_shared(smem);
    asm volatile("cp.async.ca.shared.global [%0], [%1], 16;" :: "r"(s), "l"(g));
}
__device__ __forceinline__ void cp8(void* smem, const void* g) {
    uint32_t s = (uint32_t)__cvta_generic_to_shared(smem);
    asm volatile("cp.async.ca.shared.global [%0], [%1], 8;" :: "r"(s), "l"(g));
}

// ---------------------------------------------------------------------------
// One-time weight conversions
// ---------------------------------------------------------------------------
__global__ void __launch_bounds__(256) wcvt(const float* __restrict__ W, __half* __restrict__ O) {
    int i = blockIdx.x * 256 + threadIdx.x;
    #pragma unroll
    for (int r = 0; r < 2; r++) {
        int idx = i + r * 110592;
        float4 v = *(const float4*)(W + idx*4);
        __half2 p0 = __floats2half2_rn(v.x, v.y);
        __half2 p1 = __floats2half2_rn(v.z, v.w);
        uint2 o; o.x = *(uint32_t*)&p0; o.y = *(uint32_t*)&p1;
        *(uint2*)(O + idx*4) = o;
    }
}

// conv weights OIHW f32 -> chunk-major f16: [ch][oc][tap*16 + c], stride 152
__global__ void __launch_bounds__(256) wcvtw(const float* __restrict__ w2,
        const float* __restrict__ w3, const float* __restrict__ w4) {
    for (int i = threadIdx.x + blockIdx.x*256; i < 2*32*152; i += gridDim.x*256) {
        int ch = i / (32*152);
        int r2 = i - ch*(32*152);
        int oc = r2 / 152, r = r2 - oc*152;
        float f = 0.f;
        if (r < 144) {
            int tap = r>>4, c = r&15;
            int ky = tap/3, kx = tap - ky*3;
            f = w2[((oc*32 + ch*16 + c)*3+ky)*3+kx];
        }
        g_wc2[i] = __float2half_rn(f);
    }
    for (int i = threadIdx.x + blockIdx.x*256; i < 4*32*152; i += gridDim.x*256) {
        int set = i / (32*152);
        int r2 = i - set*(32*152);
        int oc = r2 / 152, r = r2 - oc*152;
        const float* W = (set >> 1) ? w4 : w3;
        int ch = set & 1;
        float f = 0.f;
        if (r < 144) {
            int tap = r>>4, c = r&15;
            int ky = tap/3, kx = tap - ky*3;
            f = W[((oc*32 + ch*16 + c)*3+ky)*3+kx];
        }
        g_wc34[i] = __float2half_rn(f);
    }
}

// ---------------------------------------------------------------------------
// conv1 (unchanged)
// ---------------------------------------------------------------------------
template<int IH, int OH, int BAND>
__global__ void __launch_bounds__(256) conv1_f16(const float* __restrict__ in,
        const float* __restrict__ wgt, const float* __restrict__ bias,
        __half* __restrict__ out)
{
    constexpr int OW = OH, IW = IH;
    constexpr int RW = (IW+2)*4;
    constexpr int ROWS = 2*BAND + 1;
    constexpr int SIN = ROWS*RW;
    constexpr int APAD = 56;
    constexpr int NPIX = BAND*OW;
    constexpr int NT8 = (NPIX+7)/8;
    constexpr int NTW = (NT8+3)/4;
    constexpr int OHW = OH*OW;

    extern __shared__ __half sh[];
    __half* s_in = sh;
    __half* s_w  = sh + SIN;

    const int tid = threadIdx.x;
    const int n0 = blockIdx.x;
    const int oy0 = blockIdx.y * BAND;
    const int ybase = 2*oy0 - 1;

    for (int i = tid; i < SIN/8; i += 256) ((uint4*)s_in)[i] = make_uint4(0,0,0,0);

    for (int i = tid; i < 32*48; i += 256) {
        int oc = i/48, r = i - oc*48;
        int ky = r>>4, rr = r&15, kx = rr>>2, ic = rr&3;
        float v = (kx < 3) ? wgt[((oc*4+ic)*3+ky)*3+kx] : 0.f;
        s_w[oc*APAD + r] = __float2half_rn(v);
    }
    __syncthreads();

    const int y_lo = (ybase < 0) ? 0 : ybase;
    int y_hi = ybase + ROWS - 1; if (y_hi > IH-1) y_hi = IH-1;
    const int nrows = y_hi - y_lo + 1;

    for (int i = tid; i < nrows*IW; i += 256) {
        int x = i % IW; int yy = i / IW; int y = y_lo + yy;
        const float* p = in + (((size_t)n0*4)*IH + y)*IW + x;
        __half2 h01 = __floats2half2_rn(p[0], p[(size_t)IH*IW]);
        __half2 h23 = __floats2half2_rn(p[2*(size_t)IH*IW], p[3*(size_t)IH*IW]);
        __half* d = s_in + (y - ybase)*RW + (x+1)*4;
        *(__half2*)d = h01; *(__half2*)(d+2) = h23;
    }
    __syncthreads();

    const int lane = tid & 31, warp = tid >> 5;
    const int m0 = (warp & 1)*16;
    const int ng = warp >> 1;
    const int gq = lane >> 2, tq = lane & 3;

    int pixbase[NTW];
    #pragma unroll
    for (int j = 0; j < NTW; j++) {
        int tile = ng + 4*j;
        int p = tile*8 + gq;
        int pp = (p < NPIX) ? p : 0;
        int dy = pp / OW, ox = pp - dy*OW;
        pixbase[j] = 2*dy*RW + 8*ox + 2*tq;
    }

    float4 acc[NTW];
    #pragma unroll
    for (int j = 0; j < NTW; j++) acc[j] = make_float4(0.f,0.f,0.f,0.f);

    const __half* swr = s_w + (m0 + gq)*APAD + 2*tq;
    #pragma unroll
    for (int s = 0; s < 3; s++) {
        uint32_t a0 = *(const uint32_t*)(swr + s*16);
        uint32_t a1 = *(const uint32_t*)(swr + s*16 + 8*APAD);
        uint32_t a2 = *(const uint32_t*)(swr + s*16 + 8);
        uint32_t a3 = *(const uint32_t*)(swr + s*16 + 8*APAD + 8);
        int off = s*RW;
        #pragma unroll
        for (int j = 0; j < NTW; j++) {
            const __half* bp = s_in + pixbase[j] + off;
            mma16(acc[j], a0, a1, a2, a3,
                  *(const uint32_t*)bp, *(const uint32_t*)(bp + 8));
        }
    }

    const int oc = m0 + gq;
    const float b0v = __ldg(&bias[oc]);
    const float b8v = __ldg(&bias[oc+8]);
    __half* ob0 = out + ((size_t)n0*OHW + oy0*OW)*32;

    #pragma unroll
    for (int j = 0; j < NTW; j++) {
        int tile = ng + 4*j;
        if (tile >= NT8) continue;
        int pc = tile*8 + tq*2;
        if (pc < NPIX) {
            ob0[pc*32 + oc]   = __float2half_rn(eluf(acc[j].x + b0v));
            ob0[pc*32 + oc+8] = __float2half_rn(eluf(acc[j].z + b8v));
        }
        if (pc+1 < NPIX) {
            ob0[(pc+1)*32 + oc]   = __float2half_rn(eluf(acc[j].y + b0v));
            ob0[(pc+1)*32 + oc+8] = __float2half_rn(eluf(acc[j].w + b8v));
        }
    }
}

// ---------------------------------------------------------------------------
// conv2 v3: stride-20 slots (conflict-free, R13) + 8B cp.async staging
// (zero-ALU, R16). 168 staging threads = (pixel, piece); rows walked by
// pure stride increments. Race fix: zero -> barrier -> async stage.
// ---------------------------------------------------------------------------
#define C2XS   20
#define C2RW   (44*C2XS)          // 880
#define C2SIN  (15*C2RW)          // 13200
#define C2WSZ  (32*152)           // 4864
#define C2_SMEM ((C2SIN + C2WSZ) * 2)   // 36,128 B

__global__ void __launch_bounds__(256) conv2_f16(const __half* __restrict__ a1,
        const float* __restrict__ bias, __half* __restrict__ a2out)
{
    extern __shared__ __half sh[];
    __half* s_in = sh;
    __half* s_w  = sh + C2SIN;

    const int tid = threadIdx.x;
    const int n = blockIdx.x;
    const int oy0 = blockIdx.y * 7;
    const int ybase = 2*oy0 - 1;

    for (int i = tid; i < C2SIN/8; i += 256) ((uint4*)s_in)[i] = make_uint4(0,0,0,0);
    __syncthreads();   // zero visible before any cp.async staging lands

    const int y_lo = (ybase < 0) ? 0 : ybase;
    int y_hi = ybase + 14; if (y_hi > 41) y_hi = 41;
    const int nrows = y_hi - y_lo + 1;

    // staging: 168 threads = (px 0..41, piece 0..3); piece = 8 bytes = 4 halves
    const int su = tid;                  // 0..167 active
    const int sx = su >> 2, spiece = su & 3;
    const bool sact = tid < 168;
    const __half* gsrc0 = a1 + (((size_t)n*42 + y_lo)*42 + sx)*32 + spiece*4;
    __half* sdst0 = s_in + (y_lo - ybase)*C2RW + (sx+1)*C2XS + spiece*4;

    const int lane = tid & 31, warp = tid >> 5;
    const int m0 = (warp & 1)*16;
    const int ng = warp >> 1;
    const int gq = lane >> 2, tq = lane & 3;
    const int oc = m0 + gq;

    int pixbase[5];
    #pragma unroll
    for (int j = 0; j < 5; j++) {
        int tile = ng + 4*j;
        int p = tile*8 + gq;
        int pp = (p < 147) ? p : 0;
        int dy = pp / 21, ox = pp - dy*21;
        pixbase[j] = 2*dy*C2RW + 2*ox*C2XS + 2*tq;
    }
    float4 acc[5];
    #pragma unroll
    for (int j = 0; j < 5; j++) acc[j] = make_float4(0.f,0.f,0.f,0.f);

    #pragma unroll
    for (int ch = 0; ch < 2; ch++) {
        if (ch) __syncthreads();     // prior mma reads done before overwrite
        for (int i = tid; i < C2WSZ/8; i += 256)
            cp16((uint4*)s_w + i, (const uint4*)(g_wc2 + ch*C2WSZ) + i);
        if (sact) {
            const __half* gs = gsrc0 + ch*16;
            __half* ds = sdst0;
            #pragma unroll
            for (int yy = 0; yy < 15; yy++) {
                if (yy < nrows) cp8(ds, gs);
                gs += 42*32;
                ds += C2RW;
            }
        }
        asm volatile("cp.async.commit_group;");
        asm volatile("cp.async.wait_group 0;");
        __syncthreads();

        const __half* swr = s_w + oc*152 + 2*tq;
        #pragma unroll
        for (int tap = 0; tap < 9; tap++) {
            uint32_t a0 = *(const uint32_t*)(swr + tap*16);
            uint32_t a1r = *(const uint32_t*)(swr + tap*16 + 8*152);
            uint32_t a2r = *(const uint32_t*)(swr + tap*16 + 8);
            uint32_t a3r = *(const uint32_t*)(swr + tap*16 + 8*152 + 8);
            int ky = tap/3, kx = tap - ky*3;
            int off = ky*C2RW + kx*C2XS;
            #pragma unroll
            for (int j = 0; j < 5; j++) {
                const __half* bp = s_in + pixbase[j] + off;
                mma16(acc[j], a0, a1r, a2r, a3r,
                      *(const uint32_t*)bp, *(const uint32_t*)(bp + 8));
            }
        }
    }

    const float b0v = __ldg(&bias[oc]);
    const float b8v = __ldg(&bias[oc+8]);
    __half* ob0 = a2out + ((size_t)n*441 + oy0*21)*32;
    #pragma unroll
    for (int j = 0; j < 5; j++) {
        int tile = ng + 4*j;
        if (tile >= 19) continue;
        int pc = tile*8 + tq*2;
        if (pc < 147) {
            ob0[pc*32 + oc]   = __float2half_rn(eluf(acc[j].x + b0v));
            ob0[pc*32 + oc+8] = __float2half_rn(eluf(acc[j].z + b8v));
        }
        if (pc+1 < 147) {
            ob0[(pc+1)*32 + oc]   = __float2half_rn(eluf(acc[j].y + b0v));
            ob0[(pc+1)*32 + oc+8] = __float2half_rn(eluf(acc[j].w + b8v));
        }
    }
}

// ---------------------------------------------------------------------------
// Fused conv3 + conv4, IC-chunked (R14 version — unchanged)
// ---------------------------------------------------------------------------
#define RW3C   460
#define SIN3C  5984
#define RW4C   260
#define PL4    3380
#define W34OFF (SIN3C + 2*PL4)
#define C34_SMEM ((W34OFF + 32*152) * 2)   // 35,216 B

template<int NTWP>
__device__ __forceinline__ void conv3_pass(const __half* __restrict__ a2,
        __half* __restrict__ s_in, __half* __restrict__ s_c4,
        __half* __restrict__ s_w, int n, int tid, int pass,
        int ng, int gq, int tq, int oc, float b0v, float b8v)
{
    const int npix  = pass ? 55 : 66;
    const int oyb   = pass ? 6 : 0;
    const int ybase = pass ? 11 : -1;
    const int ylo   = pass ? 11 : 0;
    const int yhi   = pass ? 20 : 11;
    const int nrows = yhi - ylo + 1;

    int pixbase[NTWP];
    #pragma unroll
    for (int j = 0; j < NTWP; j++) {
        int p = (ng + 4*j)*8 + gq;
        int pp = (p < npix) ? p : 0;
        int dy = pp / 11, ox = pp - dy*11;
        pixbase[j] = 2*dy*RW3C + 2*ox*20 + 2*tq;
    }
    float4 acc[NTWP];
    #pragma unroll
    for (int j = 0; j < NTWP; j++) acc[j] = make_float4(0.f,0.f,0.f,0.f);

    #pragma unroll
    for (int ch = 0; ch < 2; ch++) {
        __syncthreads();
        if (ch == 0) {
            for (int i = tid; i < SIN3C/8; i += 256) ((uint4*)s_in)[i] = make_uint4(0,0,0,0);
        }
        for (int i = tid; i < (32*152)/8; i += 256)
            ((uint4*)s_w)[i] = ((const uint4*)(g_wc34 + ch*32*152))[i];
        __syncthreads();
        for (int i = tid; i < nrows*21*4; i += 256) {
            int g = i & 3, q = i >> 2;
            int x = q % 21; int yy = q / 21;
            int y = ylo + yy;
            uint2 v = *(const uint2*)(a2 + (((size_t)n*21 + y)*21 + x)*32 + ch*16 + g*4);
            *(uint2*)(s_in + (y - ybase)*RW3C + (x+1)*20 + g*4) = v;
        }
        __syncthreads();

        const __half* swr = s_w + oc*152 + 2*tq;
        #pragma unroll
        for (int tap = 0; tap < 9; tap++) {
            uint32_t a0 = *(const uint32_t*)(swr + tap*16);
            uint32_t a1r = *(const uint32_t*)(swr + tap*16 + 8*152);
            uint32_t a2r = *(const uint32_t*)(swr + tap*16 + 8);
            uint32_t a3r = *(const uint32_t*)(swr + tap*16 + 8*152 + 8);
            int ky = tap/3, kx = tap - ky*3;
            int off = ky*RW3C + kx*20;
            #pragma unroll
            for (int j = 0; j < NTWP; j++) {
                const __half* bp = s_in + pixbase[j] + off;
                mma16(acc[j], a0, a1r, a2r, a3r,
                      *(const uint32_t*)bp, *(const uint32_t*)(bp + 8));
            }
        }
    }

    __half* plane = s_c4 + (oc >> 4)*PL4;
    const int cl = oc & 15;
    #pragma unroll
    for (int j = 0; j < NTWP; j++) {
        int pc = (ng + 4*j)*8 + tq*2;
        #pragma unroll
        for (int u = 0; u < 2; u++) {
            int p = pc + u;
            if (p < npix) {
                int y = p / 11, x = p - y*11;
                __half* d = plane + (oyb + y + 1)*RW4C + (x+1)*20;
                float v0 = (u == 0) ? acc[j].x : acc[j].y;
                float v8 = (u == 0) ? acc[j].z : acc[j].w;
                d[cl]   = __float2half_rn(eluf(v0 + b0v));
                d[cl+8] = __float2half_rn(eluf(v8 + b8v));
            }
        }
    }
}

__global__ void __launch_bounds__(256) conv34_f16(const __half* __restrict__ a2,
        const float* __restrict__ b3f, const float* __restrict__ b4f,
        __half* __restrict__ xf)
{
    extern __shared__ __half sh[];
    __half* s_in = sh;
    __half* s_c4 = sh + SIN3C;
    __half* s_w  = sh + W34OFF;

    const int tid = threadIdx.x;
    const int n = blockIdx.x;

    for (int i = tid; i < 2*PL4/8; i += 256) ((uint4*)s_c4)[i] = make_uint4(0,0,0,0);

    const int lane = tid & 31, warp = tid >> 5;
    const int m0 = (warp & 1)*16;
    const int ng = warp >> 1;
    const int gq = lane >> 2, tq = lane & 3;
    const int oc = m0 + gq;

    const float b30 = __ldg(&b3f[oc]);
    const float b38 = __ldg(&b3f[oc+8]);

    conv3_pass<3>(a2, s_in, s_c4, s_w, n, tid, 0, ng, gq, tq, oc, b30, b38);
    conv3_pass<2>(a2, s_in, s_c4, s_w, n, tid, 1, ng, gq, tq, oc, b30, b38);

    int pixbase[2];
    #pragma unroll
    for (int j = 0; j < 2; j++) {
        int tile = ng + 4*j;
        int p = tile*8 + gq;
        int pp = (p < 36) ? p : 0;
        int dy = pp / 6, ox = pp - dy*6;
        pixbase[j] = 2*dy*RW4C + 2*ox*20 + 2*tq;
    }
    float4 acc[2];
    acc[0] = make_float4(0.f,0.f,0.f,0.f); acc[1] = acc[0];

    #pragma unroll
    for (int ch = 0; ch < 2; ch++) {
        __syncthreads();
        for (int i = tid; i < (32*152)/8; i += 256)
            ((uint4*)s_w)[i] = ((const uint4*)(g_wc34 + (2+ch)*32*152))[i];
        __syncthreads();
        const __half* plane = s_c4 + ch*PL4;
        const __half* swr = s_w + oc*152 + 2*tq;
        #pragma unroll
        for (int tap = 0; tap < 9; tap++) {
            uint32_t a0 = *(const uint32_t*)(swr + tap*16);
            uint32_t a1r = *(const uint32_t*)(swr + tap*16 + 8*152);
            uint32_t a2r = *(const uint32_t*)(swr + tap*16 + 8);
            uint32_t a3r = *(const uint32_t*)(swr + tap*16 + 8*152 + 8);
            int ky = tap/3, kx = tap - ky*3;
            int off = ky*RW4C + kx*20;
            #pragma unroll
            for (int j = 0; j < 2; j++) {
                const __half* bp = plane + pixbase[j] + off;
                mma16(acc[j], a0, a1r, a2r, a3r,
                      *(const uint32_t*)bp, *(const uint32_t*)(bp + 8));
            }
        }
    }

    const float b0v = __ldg(&b4f[oc]);
    const float b8v = __ldg(&b4f[oc+8]);
    __half* ob = xf + (size_t)n*1152;
    #pragma unroll
    for (int j = 0; j < 2; j++) {
        int tile = ng + 4*j;
        if (tile >= 5) continue;
        int pc = tile*8 + tq*2;
        if (pc < 36) {
            ob[oc*36 + pc]     = __float2half_rn(eluf(acc[j].x + b0v));
            ob[(oc+8)*36 + pc] = __float2half_rn(eluf(acc[j].z + b8v));
        }
        if (pc+1 < 36) {
            ob[oc*36 + pc+1]     = __float2half_rn(eluf(acc[j].y + b0v));
            ob[(oc+8)*36 + pc+1] = __float2half_rn(eluf(acc[j].w + b8v));
        }
    }
}

// ---------------------------------------------------------------------------
// gi[2048,768] = xf(f16) @ Wih(f16)^T + b_ih — 2-stage cp.async pipeline.
// ---------------------------------------------------------------------------
__global__ void __launch_bounds__(256) gemm_f16(const __half* __restrict__ A,
        const __half* __restrict__ B, const float* __restrict__ bias,
        float* __restrict__ C)
{
    constexpr int ST = 48;
    __shared__ __half As[2][64*ST], Bs[2][64*ST];
    const int bm = blockIdx.y*64, bn = blockIdx.x*64;
    const int tid = threadIdx.x, lane = tid&31, warp = tid>>5;
    const int wm = (warp&1)*32, wn = (warp>>1)*16;
    const int gq = lane>>2, tq = lane&3;
    const int ldr = tid>>2, ldc = (tid&3)*8;

    const __half* Ag = A + (size_t)(bm+ldr)*FEAT + ldc;
    const __half* Bg = B + (size_t)(bn+ldr)*FEAT + ldc;

    float4 acc[2][2];
    #pragma unroll
    for (int i = 0; i < 2; i++)
        #pragma unroll
        for (int j = 0; j < 2; j++) acc[i][j] = make_float4(0.f,0.f,0.f,0.f);

    cp16(&As[0][ldr*ST + ldc], Ag);
    cp16(&Bs[0][ldr*ST + ldc], Bg);
    asm volatile("cp.async.commit_group;");

    #pragma unroll 1
    for (int i = 0; i < 36; i++) {
        if (i + 1 < 36) {
            int st = (i+1)&1;
            cp16(&As[st][ldr*ST + ldc], Ag + (i+1)*32);
            cp16(&Bs[st][ldr*ST + ldc], Bg + (i+1)*32);
            asm volatile("cp.async.commit_group;");
            asm volatile("cp.async.wait_group 1;");
        } else {
            asm volatile("cp.async.wait_group 0;");
        }
        __syncthreads();
        const int cs = i&1;
        #pragma unroll
        for (int s = 0; s < 2; s++) {
            #pragma unroll
            for (int mi = 0; mi < 2; mi++) {
                const __half* ap = &As[cs][(wm + mi*16 + gq)*ST + s*16 + 2*tq];
                uint32_t a0 = *(const uint32_t*)ap;
                uint32_t a1 = *(const uint32_t*)(ap + 8*ST);
                uint32_t a2 = *(const uint32_t*)(ap + 8);
                uint32_t a3 = *(const uint32_t*)(ap + 8*ST + 8);
                #pragma unroll
                for (int ni = 0; ni < 2; ni++) {
                    const __half* bp = &Bs[cs][(wn + ni*8 + gq)*ST + s*16 + 2*tq];
                    mma16(acc[mi][ni], a0, a1, a2, a3,
                          *(const uint32_t*)bp, *(const uint32_t*)(bp + 8));
                }
            }
        }
        __syncthreads();
    }
    #pragma unroll
    for (int mi = 0; mi < 2; mi++) {
        #pragma unroll
        for (int ni = 0; ni < 2; ni++) {
            int row = bm + wm + mi*16 + gq;
            int col = bn + wn + ni*8 + tq*2;
            float bb0 = __ldg(&bias[col]), bb1 = __ldg(&bias[col+1]);
            C[(size_t)row*768 + col]       = acc[mi][ni].x + bb0;
            C[(size_t)row*768 + col + 1]   = acc[mi][ni].y + bb1;
            C[(size_t)(row+8)*768 + col]   = acc[mi][ni].z + bb0;
            C[(size_t)(row+8)*768 + col+1] = acc[mi][ni].w + bb1;
        }
    }
}

// ---------------------------------------------------------------------------
// Persistent GRU (frozen)
// ---------------------------------------------------------------------------
#define GRU_BLOCKS 64
#define GRU_THREADS 256

__device__ __forceinline__ void grid_barrier(unsigned target) {
    __threadfence();
    __syncthreads();
    if (threadIdx.x == 0) {
        unsigned v = atomicAdd(&g_bar_cnt, 1);
        if (v == GRU_BLOCKS - 1) {
            g_bar_cnt = 0;
            __threadfence();
            atomicAdd(&g_bar_phase, 1);
        } else {
            while ((int)(*(volatile unsigned*)&g_bar_phase - target) < 0) { __nanosleep(16); }
        }
        __threadfence();
    }
    __syncthreads();
}

__global__ void gru_kernel(const float* __restrict__ rnn_in, const float* __restrict__ mask,
                           const float* __restrict__ W_hh, const float* __restrict__ b_hh,
                           const float* __restrict__ gi_all, float* __restrict__ outs,
                           float* __restrict__ hfin) {
    __shared__ float s_w[12*256];
    __shared__ float s_h[32*256];
    __shared__ float s_p[3*256];

    const int tid = threadIdx.x;
    const int bx  = blockIdx.x;

    for (int i = tid; i < 12*64; i += GRU_THREADS) {
        int rl = i >> 6, kq = i & 63;
        int gate = rl >> 2, gj2 = rl & 3;
        float4 w = *(const float4*)&W_hh[(size_t)(gate*256 + bx*4 + gj2)*256 + kq*4];
        *(float4*)&s_w[rl*256 + kq*4] = w;
    }
    if (bx == 0) {
        for (int i = tid; i < BB*HID; i += GRU_THREADS) g_h[0][i] = rnn_in[i];
    }
    unsigned tgt = *(volatile unsigned*)&g_bar_phase;
    grid_barrier(++tgt);

    const int half = tid >> 7;
    const int r    = tid & 127;
    const int gj = r >> 5, b = r & 31;
    const int g = bx*4 + gj;
    const int c = b & 7;
    const float br = __ldg(&b_hh[g]);
    const float bz = __ldg(&b_hh[256 + g]);
    const float bn = __ldg(&b_hh[512 + g]);

    float4* s_h4 = (float4*)s_h;
    const float4* s_w4 = (const float4*)s_w;

    for (int t = 0; t < TT; t++) {
        float gir = 0.f, giz = 0.f, gin = 0.f;
        if (tid < 128) {
            const float* gi = gi_all + (size_t)(t*32 + b)*768;
            gir = __ldg(&gi[g]); giz = __ldg(&gi[256 + g]); gin = __ldg(&gi[512 + g]);
        }
        const float* hprev = g_h[t & 1];
        for (int i = tid; i < 32*64; i += GRU_THREADS) {
            int bb = i >> 6, kq = i & 63;
            float m = __ldg(&mask[t*32 + bb]);
            float4 hv = __ldcg((const float4*)&hprev[bb*256 + kq*4]);
            hv.x *= m; hv.y *= m; hv.z *= m; hv.w *= m;
            s_h4[bb*64 + (kq ^ (bb & 7))] = hv;
        }
        __syncthreads();

        float4 ar = make_float4(0.f,0.f,0.f,0.f), az = ar, an = ar;
        const float4* hrow = s_h4 + b*64;
        const float4* wr4 = s_w4 + (0 + gj)*64;
        const float4* wz4 = s_w4 + (4 + gj)*64;
        const float4* wn4 = s_w4 + (8 + gj)*64;
        #pragma unroll 8
        for (int kq = 0; kq < 32; kq++) {
            int kqg = half*32 + kq;
            float4 h = hrow[kqg ^ c];
            float4 wr = wr4[kqg], wz = wz4[kqg], wn = wn4[kqg];
            ar.x += h.x*wr.x; ar.y += h.y*wr.y; ar.z += h.z*wr.z; ar.w += h.w*wr.w;
            az.x += h.x*wz.x; az.y += h.y*wz.y; az.z += h.z*wz.z; az.w += h.w*wz.w;
            an.x += h.x*wn.x; an.y += h.y*wn.y; an.z += h.z*wn.z; an.w += h.w*wn.w;
        }
        s_p[0*256 + tid] = ar.x + ar.y + ar.z + ar.w;
        s_p[1*256 + tid] = az.x + az.y + az.z + az.w;
        s_p[2*256 + tid] = an.x + an.y + an.z + an.w;
        __syncthreads();
        if (tid < 128) {
            float ghr = s_p[0*256 + tid] + s_p[0*256 + tid + 128] + br;
            float ghz = s_p[1*256 + tid] + s_p[1*256 + tid + 128] + bz;
            float ghn = s_p[2*256 + tid] + s_p[2*256 + tid + 128] + bn;
            float rr = 1.f / (1.f + expf(-(gir + ghr)));
            float zz = 1.f / (1.f + expf(-(giz + ghz)));
            float nn = tanhf(gin + rr*ghn);
            float hold = s_h[b*256 + (((g>>2) ^ c)<<2) + (g&3)];
            float hn = (1.f - zz)*nn + zz*hold;
            g_h[(t + 1) & 1][b*256 + g] = hn;
            outs[(size_t)(t*32 + b)*256 + g] = hn;
            if (t == TT - 1) hfin[b*256 + g] = hn;
        }
        grid_barrier(++tgt);
    }
}

// ---------------------------------------------------------------------------
// Heads
// ---------------------------------------------------------------------------
__global__ void heads_kernel(const float* __restrict__ outs, const int* __restrict__ actions,
                             const float* __restrict__ Wc, const float* __restrict__ bc,
                             const float* __restrict__ Wa, const float* __restrict__ ba,
                             float* __restrict__ d_out) {
    int warp = (blockIdx.x * blockDim.x + threadIdx.x) >> 5;
    int lane = threadIdx.x & 31;
    if (warp >= NTB) return;
    const float* o = outs + (size_t)warp * 256;

    float acc[13];
    #pragma unroll
    for (int g = 0; g < 13; g++) acc[g] = 0.f;
    #pragma unroll
    for (int i = 0; i < 8; i++) {
        int k = lane + 32*i;
        float x = o[k];
        acc[0] += x * __ldg(&Wc[k]);
        #pragma unroll
        for (int g = 0; g < 12; g++) acc[1 + g] += x * __ldg(&Wa[g*256 + k]);
    }
    #pragma unroll
    for (int g = 0; g < 13; g++) {
        #pragma unroll
        for (int s = 16; s > 0; s >>= 1) acc[g] += __shfl_xor_sync(0xFFFFFFFFu, acc[g], s);
    }
    if (lane == 0) {
        float v = acc[0] + bc[0];
        float l[12];
        float m = -1e30f;
        #pragma unroll
        for (int g = 0; g < 12; g++) { l[g] = acc[1 + g] + ba[g]; m = fmaxf(m, l[g]); }
        float s = 0.f, sl = 0.f;
        #pragma unroll
        for (int g = 0; g < 12; g++) {
            float e = expf(l[g] - m);
            s += e; sl += e * l[g];
        }
        float logZ = m + logf(s);
        int a = actions[warp];
        d_out[warp]        = v;
        d_out[2048 + warp] = (float)a;
        d_out[4096 + warp] = l[a] - logZ;
        d_out[6144 + warp] = logZ - sl / s;
    }
}

// ---------------------------------------------------------------------------
// Host launcher
// ---------------------------------------------------------------------------
#define C1_SMEM ((13*344 + 32*56) * 2)

extern "C" void kernel_launch(void* const* d_in, const int* in_sizes, int n_in,
                              void* d_out, int out_size) {
    const float* inputs = (const float*)d_in[0];
    const float* rnn_in = (const float*)d_in[1];
    const float* mask   = (const float*)d_in[2];
    const int*   actions= (const int*)  d_in[3];
    const float* w1 = (const float*)d_in[4];  const float* b1 = (const float*)d_in[5];
    const float* w2 = (const float*)d_in[6];  const float* b2 = (const float*)d_in[7];
    const float* w3 = (const float*)d_in[8];  const float* b3 = (const float*)d_in[9];
    const float* w4 = (const float*)d_in[10]; const float* b4 = (const float*)d_in[11];
    const float* W_ih = (const float*)d_in[12];
    const float* W_hh = (const float*)d_in[13];
    const float* b_ih = (const float*)d_in[14];
    const float* b_hh = (const float*)d_in[15];
    const float* Wc = (const float*)d_in[16]; const float* bc = (const float*)d_in[17];
    const float* Wa = (const float*)d_in[18]; const float* ba = (const float*)d_in[19];
    float* out = (float*)d_out;

    __half *a1, *a2, *xf, *wih;
    float *gi, *outs;
    cudaGetSymbolAddress((void**)&a1, g_a1);
    cudaGetSymbolAddress((void**)&a2, g_a2);
    cudaGetSymbolAddress((void**)&xf, g_xf);
    cudaGetSymbolAddress((void**)&wih, g_wih);
    cudaGetSymbolAddress((void**)&gi, g_gi);
    cudaGetSymbolAddress((void**)&outs, g_outs);

    cudaFuncSetAttribute((conv1_f16<84,42,6>), cudaFuncAttributeMaxDynamicSharedMemorySize, C1_SMEM);
    cudaFuncSetAttribute(conv2_f16,            cudaFuncAttributeMaxDynamicSharedMemorySize, C2_SMEM);
    cudaFuncSetAttribute(conv34_f16,           cudaFuncAttributeMaxDynamicSharedMemorySize, C34_SMEM);

    wcvt<<<432, 256>>>(W_ih, wih);
    wcvtw<<<16, 256>>>(w2, w3, w4);
    conv1_f16<84,42,6> <<<dim3(NTB,7), 256, C1_SMEM>>>(inputs, w1, b1, a1);
    conv2_f16          <<<dim3(NTB,3), 256, C2_SMEM>>>(a1, b2, a2);
    conv34_f16         <<<NTB, 256, C34_SMEM>>>(a2, b3, b4, xf);

    gemm_f16<<<dim3(768/64, 2048/64), 256>>>(xf, wih, b_ih, gi);

    gru_kernel<<<GRU_BLOCKS, GRU_THREADS>>>(rnn_in, mask, W_hh, b_hh, gi, outs, out + 8192);

    heads_kernel<<<256, 256>>>(outs, actions, Wc, bc, Wa, ba, out);
}